// round 1
// baseline (speedup 1.0000x reference)
#include <cuda_runtime.h>

// ---------------- problem constants ----------------
#define BATCH   256
#define NSAMP   16000
#define CCH     32
#define KTAP    64
#define NCHUNK  125          // 128-sample chunks covering 16000 samples
#define TSTEPS  124
#define HID     50
#define OUT     10
#define ANS     10

// ---------------- device scratch (no allocs allowed) ----------------
__device__ float S_buf[BATCH * NCHUNK * CCH];        // per-chunk relu sums, ~16.4 MB
__device__ float SufW_g[CCH * (ANS + 1) * HID];      // suffix sums of W_bushy, layout [(c*11+a)*50 + h]

// ---------------- kernel A: suffix sums of W_bushy ----------------
// W_bushy: [HID, C*ANS] row-major, col index = c*10 + a.
// SufW[(c*11+a)*50 + h] = sum_{a'>=a} W_bushy[h, c*10+a'],  SufW[...a=10...] = 0
__global__ void sufw_kernel(const float* __restrict__ Wb) {
    int id = blockIdx.x * 256 + threadIdx.x;
    if (id >= HID * CCH) return;
    int h = id / CCH;
    int c = id % CCH;
    SufW_g[(c * 11 + 10) * HID + h] = 0.0f;
    float s = 0.0f;
    #pragma unroll
    for (int a = ANS - 1; a >= 0; a--) {
        s += Wb[h * (CCH * ANS) + c * ANS + a];
        SufW_g[(c * 11 + a) * HID + h] = s;
    }
}

// ---------------- kernel B: fused gammatone conv + relu + chunk-sum ----------------
// grid (NCHUNK, BATCH), 256 threads. lane = channel, warp = position group (8 groups x 16 pos).
// S_buf[(b*125 + j)*32 + c] = sum_{w in chunk j} relu( sum_k audio[n+k-31] * ker[c][k] )
__global__ void __launch_bounds__(256, 2) conv_pool_kernel(const float* __restrict__ audio,
                                                           const float* __restrict__ gt) {
    const int j = blockIdx.x;
    const int b = blockIdx.y;
    __shared__ float s_audio[192];           // samples j*128-31 .. j*128+159  (191 used)
    __shared__ float s_ker[64 * 33];         // swizzled: [k*33 + c] (conflict-free both ways)
    __shared__ float s_part[256];

    const int tid = threadIdx.x;

    // stage kernels swizzled (global idx t = c*64 + k)
    for (int t = tid; t < CCH * KTAP; t += 256) {
        int c = t >> 6, k = t & 63;
        s_ker[k * 33 + c] = gt[t];
    }
    // stage audio window with zero padding (SAME: pad_low=31)
    const int nbase = j * 128 - 31;
    for (int i = tid; i < 191; i += 256) {
        int n = nbase + i;
        s_audio[i] = (n >= 0 && n < NSAMP) ? audio[b * NSAMP + n] : 0.0f;
    }
    __syncthreads();

    const int c = tid & 31;    // channel = lane
    const int g = tid >> 5;    // position group

    // taps in registers
    float kreg[KTAP];
    #pragma unroll
    for (int k = 0; k < KTAP; k++) kreg[k] = s_ker[k * 33 + c];

    float acc = 0.0f;
    const int w0 = g * 16;
    #pragma unroll 1
    for (int p = 0; p < 16; p++) {
        const float* a = s_audio + w0 + p;   // broadcast across the warp (same address all lanes)
        float y0 = 0.f, y1 = 0.f, y2 = 0.f, y3 = 0.f;
        #pragma unroll
        for (int k = 0; k < KTAP; k += 4) {
            y0 = fmaf(a[k],     kreg[k],     y0);
            y1 = fmaf(a[k + 1], kreg[k + 1], y1);
            y2 = fmaf(a[k + 2], kreg[k + 2], y2);
            y3 = fmaf(a[k + 3], kreg[k + 3], y3);
        }
        float y = (y0 + y1) + (y2 + y3);
        acc += fmaxf(y, 0.0f);
    }
    s_part[tid] = acc;
    __syncthreads();

    if (tid < 32) {
        float s = 0.0f;
        #pragma unroll
        for (int gg = 0; gg < 8; gg++) s += s_part[gg * 32 + tid];
        S_buf[(b * NCHUNK + j) * CCH + tid] = s;
    }
}

// ---------------- kernel C: 124-step LIF scan, one block per batch element ----------------
__global__ void __launch_bounds__(64) snn_kernel(const float* __restrict__ Wic,
                                                 const float* __restrict__ Wac,
                                                 float* __restrict__ out, int half) {
    const int b = blockIdx.x;
    __shared__ float sS[NCHUNK * CCH];       // 4000 floats: all chunk sums for this batch
    __shared__ float sWic[HID * HID];        // transposed: [i*50 + h]
    __shared__ float sWac[HID * OUT];        // transposed: [i*10 + o]
    __shared__ int   sOff[CCH];              // per-channel SufW row offset this step
    __shared__ float sSpkB[HID];
    __shared__ float sSpkIC[HID];

    const int tid = threadIdx.x;

    for (int x = tid; x < NCHUNK * CCH; x += 64) sS[x] = S_buf[b * (NCHUNK * CCH) + x];
    for (int x = tid; x < HID * HID; x += 64) {
        int h = x / HID, i = x % HID;
        sWic[i * HID + h] = Wic[x];
    }
    for (int x = tid; x < OUT * HID; x += 64) {
        int o = x / HID, i = x % HID;
        sWac[i * OUT + o] = Wac[x];
    }
    __syncthreads();

    float memB = 0.0f, memIC = 0.0f, memAC = 0.0f;
    const float beta = 0.95f;

    for (int t = 0; t < TSTEPS; t++) {
        // --- auditory nerve: count firing scales -> suffix index ---
        if (tid < CCH) {
            float env = (sS[t * CCH + tid] + sS[(t + 1) * CCH + tid]) * (1.0f / 256.0f);
            int cnt = 0;
            #pragma unroll
            for (int a = 0; a < ANS; a++) {
                float sc = 0.5f + (float)a * (1.0f / 9.0f);   // linspace(0.5, 1.5, 10)
                cnt += (env * sc - 0.5f) > 0.0f;
            }
            sOff[tid] = (tid * 11 + (ANS - cnt)) * HID;
        }
        __syncthreads();

        // --- bushy LIF: 32 suffix-sum lookups instead of 320-wide matvec ---
        if (tid < HID) {
            float a0 = 0.f, a1 = 0.f;
            #pragma unroll
            for (int cc = 0; cc < CCH; cc += 2) {
                a0 += __ldg(&SufW_g[sOff[cc] + tid]);
                a1 += __ldg(&SufW_g[sOff[cc + 1] + tid]);
            }
            memB = beta * memB + (a0 + a1);
            float spk = (memB - 1.0f) > 0.0f ? 1.0f : 0.0f;
            memB -= spk;
            sSpkB[tid] = spk;
        }
        __syncthreads();

        // --- inferior colliculus LIF ---
        if (tid < HID) {
            float a0 = 0.f, a1 = 0.f;
            #pragma unroll
            for (int i = 0; i < HID; i += 2) {
                a0 = fmaf(sSpkB[i],     sWic[i * HID + tid],       a0);
                a1 = fmaf(sSpkB[i + 1], sWic[(i + 1) * HID + tid], a1);
            }
            memIC = beta * memIC + (a0 + a1);
            float spk = (memIC - 1.0f) > 0.0f ? 1.0f : 0.0f;
            memIC -= spk;
            sSpkIC[tid] = spk;
        }
        __syncthreads();

        // --- audio cortex LIF + output ---
        if (tid < OUT) {
            float a0 = 0.f, a1 = 0.f;
            #pragma unroll
            for (int i = 0; i < HID; i += 2) {
                a0 = fmaf(sSpkIC[i],     sWac[i * OUT + tid],       a0);
                a1 = fmaf(sSpkIC[i + 1], sWac[(i + 1) * OUT + tid], a1);
            }
            memAC = beta * memAC + (a0 + a1);
            float spk = (memAC - 1.0f) > 0.0f ? 1.0f : 0.0f;
            memAC -= spk;
            int idx = (b * TSTEPS + t) * OUT + tid;
            out[idx] = spk;            // spk_rec [B,T,OUT]
            out[half + idx] = memAC;   // mem_rec [B,T,OUT]
        }
        __syncthreads();
    }
}

// ---------------- launch ----------------
extern "C" void kernel_launch(void* const* d_in, const int* in_sizes, int n_in,
                              void* d_out, int out_size) {
    const float* audio = (const float*)d_in[0];
    const float* gt    = (const float*)d_in[1];
    const float* Wb    = (const float*)d_in[2];
    const float* Wic   = (const float*)d_in[3];
    const float* Wac   = (const float*)d_in[4];
    float* out = (float*)d_out;

    int B = in_sizes[0] / NSAMP;   // 256
    int half = out_size / 2;       // B*T*OUT

    sufw_kernel<<<(HID * CCH + 255) / 256, 256>>>(Wb);
    conv_pool_kernel<<<dim3(NCHUNK, B), 256>>>(audio, gt);
    snn_kernel<<<B, 64>>>(Wic, Wac, out, half);
}

// round 2
// speedup vs baseline: 1.5164x; 1.5164x over previous
#include <cuda_runtime.h>

// ---------------- problem constants ----------------
#define BATCH   256
#define NSAMP   16000
#define CCH     32
#define KTAP    64
#define NCHUNK  125          // 128-sample chunks covering 16000 samples
#define TSTEPS  124
#define HID     50
#define OUT     10
#define ANS     10

#define GROUP   4            // chunks per conv block
#define SEG     (GROUP*128)  // 512 positions per block
#define SWIN    580          // staged window length per shifted copy
#define SPITCH  592          // padded copy pitch (floats), 16B-aligned stride

// ---------------- device scratch (no allocs allowed) ----------------
__device__ float S_buf[BATCH * NCHUNK * CCH];        // per-chunk relu sums
__device__ float SufW_g[CCH * (ANS + 1) * HID];      // suffix sums of W_bushy

// ---------------- helpers ----------------
__device__ __forceinline__ unsigned s2u(const void* p) {
    return (unsigned)__cvta_generic_to_shared(p);
}
#define FFMA2(acc, a, b) \
    asm("fma.rn.f32x2 %0, %1, %2, %0;" : "+l"(acc) : "l"(a), "l"(b))
#define LDSV2(lo, hi, addr) \
    asm("ld.shared.v2.b64 {%0, %1}, [%2];" : "=l"(lo), "=l"(hi) : "r"(addr))

// ---------------- kernel A: suffix sums of W_bushy ----------------
__global__ void sufw_kernel(const float* __restrict__ Wb) {
    int id = blockIdx.x * 256 + threadIdx.x;
    if (id >= HID * CCH) return;
    int h = id / CCH;
    int c = id % CCH;
    SufW_g[(c * 11 + 10) * HID + h] = 0.0f;
    float s = 0.0f;
    #pragma unroll
    for (int a = ANS - 1; a >= 0; a--) {
        s += Wb[h * (CCH * ANS) + c * ANS + a];
        SufW_g[(c * 11 + a) * HID + h] = s;
    }
}

// ---------------- kernel B: fused gammatone conv + relu + chunk-sum (FFMA2) ----------------
// grid (32, BATCH), 256 threads. lane = channel (broadcast audio), warp g handles
// 64 contiguous positions (= half of chunk g/2) as 32 packed position-pairs.
__global__ void __launch_bounds__(256, 1) conv_pool_kernel(const float* __restrict__ audio,
                                                           const float* __restrict__ gt) {
    const int grp = blockIdx.x;
    const int b   = blockIdx.y;
    __shared__ __align__(16) float s_copy[4][SPITCH];  // 4 shifted copies of audio window
    __shared__ float s_gt[KTAP * 33];                  // swizzled taps [k*33+c]
    __shared__ float s_part[256];

    const int tid = threadIdx.x;
    const int P0  = grp * SEG;
    const float* abase = audio + b * NSAMP;

    // stage 4 shifted audio copies: s_copy[s][i] = sample(P0 - 31 + i + s), zero-padded
    #pragma unroll
    for (int s = 0; s < 4; s++) {
        for (int i = tid; i < SWIN; i += 256) {
            int n = P0 - 31 + i + s;
            s_copy[s][i] = (n >= 0 && n < NSAMP) ? abase[n] : 0.0f;
        }
    }
    // stage taps coalesced, swizzled
    for (int t = tid; t < CCH * KTAP; t += 256) {
        int c = t >> 6, k = t & 63;
        s_gt[k * 33 + c] = gt[t];
    }
    __syncthreads();

    const int c = tid & 31;   // channel = lane
    const int g = tid >> 5;   // warp id

    // duplicated packed taps: kd[k] = {t[c][k], t[c][k]}
    unsigned long long kd[KTAP];
    #pragma unroll
    for (int k = 0; k < KTAP; k++) {
        float t = s_gt[k * 33 + c];
        asm("mov.b64 %0, {%1, %1};" : "=l"(kd[k]) : "f"(t));
    }

    const unsigned sb = s2u(&s_copy[0][0]);
    const int wbase = g * 64;           // first position (within segment) for this warp
    float chunkacc = 0.0f;

    #pragma unroll 1
    for (int p = 0; p < 32; p++) {
        const int Q = wbase + 2 * p;    // window coord of position pair start
        // phase A: taps k=4m,4m+2 -> pairs start at x=Q+4m   (copy shift sA = Q&3)
        // phase B: taps k=4m+1,4m+3 -> pairs start at x=Q+1+4m (copy shift sB = (Q+1)&3)
        const int sA = Q & 3;
        const int sB = (Q + 1) & 3;
        unsigned addrA = sb + (unsigned)((sA * SPITCH + (Q - sA)) * 4);
        unsigned addrB = sb + (unsigned)((sB * SPITCH + (Q + 1 - sB)) * 4);

        unsigned long long acc0 = 0ull, acc1 = 0ull, acc2 = 0ull, acc3 = 0ull;
        #pragma unroll
        for (int m = 0; m < 16; m++) {
            unsigned long long pA0, pA1, pB0, pB1;
            LDSV2(pA0, pA1, addrA + 16u * m);
            LDSV2(pB0, pB1, addrB + 16u * m);
            FFMA2(acc0, pA0, kd[4 * m]);
            FFMA2(acc1, pB0, kd[4 * m + 1]);
            FFMA2(acc2, pA1, kd[4 * m + 2]);
            FFMA2(acc3, pB1, kd[4 * m + 3]);
        }
        // combine: y0 (position Q) = sum of lo halves, y1 (position Q+1) = hi halves
        float a0l, a0h, a1l, a1h, a2l, a2h, a3l, a3h;
        asm("mov.b64 {%0, %1}, %2;" : "=f"(a0l), "=f"(a0h) : "l"(acc0));
        asm("mov.b64 {%0, %1}, %2;" : "=f"(a1l), "=f"(a1h) : "l"(acc1));
        asm("mov.b64 {%0, %1}, %2;" : "=f"(a2l), "=f"(a2h) : "l"(acc2));
        asm("mov.b64 {%0, %1}, %2;" : "=f"(a3l), "=f"(a3h) : "l"(acc3));
        float y0 = (a0l + a1l) + (a2l + a3l);
        float y1 = (a0h + a1h) + (a2h + a3h);
        chunkacc += fmaxf(y0, 0.0f) + fmaxf(y1, 0.0f);
    }

    s_part[tid] = chunkacc;
    __syncthreads();

    // chunk cg is covered by warps 2cg and 2cg+1
    if (tid < 128) {
        int cg = tid >> 5, cc = tid & 31;
        float s = s_part[cg * 64 + cc] + s_part[cg * 64 + 32 + cc];
        int j = grp * GROUP + cg;
        if (j < NCHUNK)
            S_buf[(b * NCHUNK + j) * CCH + cc] = s;
    }
}

// ---------------- kernel C: 124-step LIF scan, one block per batch element ----------------
__global__ void __launch_bounds__(64) snn_kernel(const float* __restrict__ Wic,
                                                 const float* __restrict__ Wac,
                                                 float* __restrict__ out, int half) {
    const int b = blockIdx.x;
    __shared__ float sS[NCHUNK * CCH];
    __shared__ float sWic[HID * HID];        // transposed: [i*50 + h]
    __shared__ float sWac[HID * OUT];        // transposed: [i*10 + o]
    __shared__ int   sOff[CCH];
    __shared__ float sSpkB[HID];
    __shared__ float sSpkIC[HID];

    const int tid = threadIdx.x;

    for (int x = tid; x < NCHUNK * CCH; x += 64) sS[x] = S_buf[b * (NCHUNK * CCH) + x];
    for (int x = tid; x < HID * HID; x += 64) {
        int h = x / HID, i = x % HID;
        sWic[i * HID + h] = Wic[x];
    }
    for (int x = tid; x < OUT * HID; x += 64) {
        int o = x / HID, i = x % HID;
        sWac[i * OUT + o] = Wac[x];
    }
    __syncthreads();

    float memB = 0.0f, memIC = 0.0f, memAC = 0.0f;
    const float beta = 0.95f;

    for (int t = 0; t < TSTEPS; t++) {
        if (tid < CCH) {
            float env = (sS[t * CCH + tid] + sS[(t + 1) * CCH + tid]) * (1.0f / 256.0f);
            int cnt = 0;
            #pragma unroll
            for (int a = 0; a < ANS; a++) {
                float sc = 0.5f + (float)a * (1.0f / 9.0f);
                cnt += (env * sc - 0.5f) > 0.0f;
            }
            sOff[tid] = (tid * 11 + (ANS - cnt)) * HID;
        }
        __syncthreads();

        if (tid < HID) {
            float a0 = 0.f, a1 = 0.f;
            #pragma unroll
            for (int cc = 0; cc < CCH; cc += 2) {
                a0 += __ldg(&SufW_g[sOff[cc] + tid]);
                a1 += __ldg(&SufW_g[sOff[cc + 1] + tid]);
            }
            memB = beta * memB + (a0 + a1);
            float spk = (memB - 1.0f) > 0.0f ? 1.0f : 0.0f;
            memB -= spk;
            sSpkB[tid] = spk;
        }
        __syncthreads();

        if (tid < HID) {
            float a0 = 0.f, a1 = 0.f;
            #pragma unroll
            for (int i = 0; i < HID; i += 2) {
                a0 = fmaf(sSpkB[i],     sWic[i * HID + tid],       a0);
                a1 = fmaf(sSpkB[i + 1], sWic[(i + 1) * HID + tid], a1);
            }
            memIC = beta * memIC + (a0 + a1);
            float spk = (memIC - 1.0f) > 0.0f ? 1.0f : 0.0f;
            memIC -= spk;
            sSpkIC[tid] = spk;
        }
        __syncthreads();

        if (tid < OUT) {
            float a0 = 0.f, a1 = 0.f;
            #pragma unroll
            for (int i = 0; i < HID; i += 2) {
                a0 = fmaf(sSpkIC[i],     sWac[i * OUT + tid],       a0);
                a1 = fmaf(sSpkIC[i + 1], sWac[(i + 1) * OUT + tid], a1);
            }
            memAC = beta * memAC + (a0 + a1);
            float spk = (memAC - 1.0f) > 0.0f ? 1.0f : 0.0f;
            memAC -= spk;
            int idx = (b * TSTEPS + t) * OUT + tid;
            out[idx] = spk;
            out[half + idx] = memAC;
        }
        __syncthreads();
    }
}

// ---------------- launch ----------------
extern "C" void kernel_launch(void* const* d_in, const int* in_sizes, int n_in,
                              void* d_out, int out_size) {
    const float* audio = (const float*)d_in[0];
    const float* gt    = (const float*)d_in[1];
    const float* Wb    = (const float*)d_in[2];
    const float* Wic   = (const float*)d_in[3];
    const float* Wac   = (const float*)d_in[4];
    float* out = (float*)d_out;

    int B = in_sizes[0] / NSAMP;   // 256
    int half = out_size / 2;       // B*T*OUT

    sufw_kernel<<<(HID * CCH + 255) / 256, 256>>>(Wb);
    conv_pool_kernel<<<dim3((NCHUNK + GROUP - 1) / GROUP, B), 256>>>(audio, gt);
    snn_kernel<<<B, 64>>>(Wic, Wac, out, half);
}

// round 3
// speedup vs baseline: 2.3547x; 1.5528x over previous
#include <cuda_runtime.h>

// ---------------- problem constants ----------------
#define BATCH   256
#define NSAMP   16000
#define CCH     32
#define KTAP    64
#define NCHUNK  125          // 128-sample chunks covering 16000 samples
#define TSTEPS  124
#define HID     50
#define OUT     10
#define ANS     10

#define GROUP   4            // chunks per conv block
#define SEG     (GROUP*128)  // 512 positions per block
#define SWIN    576          // staged window length per shifted copy
#define SPITCH  592          // padded copy pitch (floats); 592*4 bytes is 16B-aligned

// ---------------- device scratch (no allocs allowed) ----------------
__device__ float S_buf[BATCH * NCHUNK * CCH];        // per-chunk relu sums
__device__ float SufW_g[CCH * (ANS + 1) * HID];      // suffix sums of W_bushy

// ---------------- helpers ----------------
__device__ __forceinline__ unsigned s2u(const void* p) {
    return (unsigned)__cvta_generic_to_shared(p);
}
#define FFMA2(acc, a, b) \
    asm("fma.rn.f32x2 %0, %1, %2, %0;" : "+l"(acc) : "l"(a), "l"(b))
#define LDSV2(lo, hi, addr) \
    asm("ld.shared.v2.b64 {%0, %1}, [%2];" : "=l"(lo), "=l"(hi) : "r"(addr))

// ---------------- kernel A: suffix sums of W_bushy ----------------
__global__ void sufw_kernel(const float* __restrict__ Wb) {
    int id = blockIdx.x * 256 + threadIdx.x;
    if (id >= HID * CCH) return;
    int h = id / CCH;
    int c = id % CCH;
    SufW_g[(c * 11 + 10) * HID + h] = 0.0f;
    float s = 0.0f;
    #pragma unroll
    for (int a = ANS - 1; a >= 0; a--) {
        s += Wb[h * (CCH * ANS) + c * ANS + a];
        SufW_g[(c * 11 + a) * HID + h] = s;
    }
}

// ---------------- kernel B: fused gammatone conv + relu + chunk-sum ----------------
// grid (32, BATCH), 256 threads. lane = channel (audio broadcast across lanes).
// Warp g covers positions [g*64, g*64+64). Each pass handles 8 positions strided
// by 4 (same 4-byte alignment class), so one LDS.128 audio group feeds up to 16
// FFMA2 instructions: 23 LDS.128 + 256 FFMA2 per pass.
__global__ void __launch_bounds__(256, 1) conv_pool_kernel(const float* __restrict__ audio,
                                                           const float* __restrict__ gt) {
    const int grp = blockIdx.x;
    const int b   = blockIdx.y;
    __shared__ __align__(16) float s_copy[4][SPITCH];  // 4 shifted copies of audio window
    __shared__ float s_gt[KTAP * 33];                  // swizzled taps [k*33+c]
    __shared__ float s_part[256];

    const int tid = threadIdx.x;
    const int P0  = grp * SEG;
    const float* abase = audio + b * NSAMP;

    // stage 4 shifted audio copies: s_copy[s][i] = sample(P0 - 31 + i + s), zero-padded
    #pragma unroll
    for (int s = 0; s < 4; s++) {
        for (int i = tid; i < SWIN; i += 256) {
            int n = P0 - 31 + i + s;
            s_copy[s][i] = (n >= 0 && n < NSAMP) ? abase[n] : 0.0f;
        }
    }
    // stage taps coalesced, swizzled
    for (int t = tid; t < CCH * KTAP; t += 256) {
        int c = t >> 6, k = t & 63;
        s_gt[k * 33 + c] = gt[t];
    }
    __syncthreads();

    const int c = tid & 31;   // channel = lane
    const int g = tid >> 5;   // warp id

    // packed tap pairs: kp[j] = {t[2j], t[2j+1]}  (32 b64 = 64 regs)
    unsigned long long kp[32];
    #pragma unroll
    for (int j = 0; j < 32; j++) {
        float t0 = s_gt[(2 * j) * 33 + c];
        float t1 = s_gt[(2 * j + 1) * 33 + c];
        asm("mov.b64 %0, {%1, %2};" : "=l"(kp[j]) : "f"(t0), "f"(t1));
    }

    const unsigned sbase = s2u(&s_copy[0][0]);
    float chunkacc = 0.0f;

    #pragma unroll 1
    for (int pass = 0; pass < 8; pass++) {
        const int h  = pass >> 2;        // 0..1 : which 32-position half
        const int c4 = pass & 3;         // copy index = position mod 4
        const int base = g * 64 + 32 * h;   // multiple of 32 -> 16B aligned
        const unsigned addr = sbase + (unsigned)((c4 * SPITCH + base) * 4);

        // 8 positions P = base + c4 + 4j, j = 0..7; two acc chains per position
        unsigned long long accL[8], accH[8];
        #pragma unroll
        for (int j = 0; j < 8; j++) { accL[j] = 0ull; accH[j] = 0ull; }

        #pragma unroll
        for (int u = 0; u < 23; u++) {
            unsigned long long lo, hi;
            LDSV2(lo, hi, addr + 16u * (unsigned)u);
            #pragma unroll
            for (int j = 0; j < 8; j++) {
                const int m = u - j;               // tap group index for this position
                if (m >= 0 && m < 16) {
                    FFMA2(accL[j], lo, kp[2 * m]);       // taps 4m, 4m+1
                    FFMA2(accH[j], hi, kp[2 * m + 1]);   // taps 4m+2, 4m+3
                }
            }
        }

        #pragma unroll
        for (int j = 0; j < 8; j++) {
            float l0, l1, h0, h1;
            asm("mov.b64 {%0, %1}, %2;" : "=f"(l0), "=f"(l1) : "l"(accL[j]));
            asm("mov.b64 {%0, %1}, %2;" : "=f"(h0), "=f"(h1) : "l"(accH[j]));
            float y = (l0 + l1) + (h0 + h1);
            chunkacc += fmaxf(y, 0.0f);
        }
    }

    s_part[tid] = chunkacc;
    __syncthreads();

    // chunk cg is covered by warps 2cg and 2cg+1
    if (tid < 128) {
        int cg = tid >> 5, cc = tid & 31;
        float s = s_part[cg * 64 + cc] + s_part[cg * 64 + 32 + cc];
        int j = grp * GROUP + cg;
        if (j < NCHUNK)
            S_buf[(b * NCHUNK + j) * CCH + cc] = s;
    }
}

// ---------------- kernel C: 124-step LIF scan, one block per batch element ----------------
__global__ void __launch_bounds__(64) snn_kernel(const float* __restrict__ Wic,
                                                 const float* __restrict__ Wac,
                                                 float* __restrict__ out, int half) {
    const int b = blockIdx.x;
    __shared__ float sS[NCHUNK * CCH];
    __shared__ float sWic[HID * HID];        // transposed: [i*50 + h]
    __shared__ float sWac[HID * OUT];        // transposed: [i*10 + o]
    __shared__ int   sOff[CCH];
    __shared__ float sSpkB[HID];
    __shared__ float sSpkIC[HID];

    const int tid = threadIdx.x;

    for (int x = tid; x < NCHUNK * CCH; x += 64) sS[x] = S_buf[b * (NCHUNK * CCH) + x];
    for (int x = tid; x < HID * HID; x += 64) {
        int h = x / HID, i = x % HID;
        sWic[i * HID + h] = Wic[x];
    }
    for (int x = tid; x < OUT * HID; x += 64) {
        int o = x / HID, i = x % HID;
        sWac[i * OUT + o] = Wac[x];
    }
    __syncthreads();

    float memB = 0.0f, memIC = 0.0f, memAC = 0.0f;
    const float beta = 0.95f;

    for (int t = 0; t < TSTEPS; t++) {
        if (tid < CCH) {
            float env = (sS[t * CCH + tid] + sS[(t + 1) * CCH + tid]) * (1.0f / 256.0f);
            int cnt = 0;
            #pragma unroll
            for (int a = 0; a < ANS; a++) {
                float sc = 0.5f + (float)a * (1.0f / 9.0f);
                cnt += (env * sc - 0.5f) > 0.0f;
            }
            sOff[tid] = (tid * 11 + (ANS - cnt)) * HID;
        }
        __syncthreads();

        if (tid < HID) {
            float a0 = 0.f, a1 = 0.f;
            #pragma unroll
            for (int cc = 0; cc < CCH; cc += 2) {
                a0 += __ldg(&SufW_g[sOff[cc] + tid]);
                a1 += __ldg(&SufW_g[sOff[cc + 1] + tid]);
            }
            memB = beta * memB + (a0 + a1);
            float spk = (memB - 1.0f) > 0.0f ? 1.0f : 0.0f;
            memB -= spk;
            sSpkB[tid] = spk;
        }
        __syncthreads();

        if (tid < HID) {
            float a0 = 0.f, a1 = 0.f;
            #pragma unroll
            for (int i = 0; i < HID; i += 2) {
                a0 = fmaf(sSpkB[i],     sWic[i * HID + tid],       a0);
                a1 = fmaf(sSpkB[i + 1], sWic[(i + 1) * HID + tid], a1);
            }
            memIC = beta * memIC + (a0 + a1);
            float spk = (memIC - 1.0f) > 0.0f ? 1.0f : 0.0f;
            memIC -= spk;
            sSpkIC[tid] = spk;
        }
        __syncthreads();

        if (tid < OUT) {
            float a0 = 0.f, a1 = 0.f;
            #pragma unroll
            for (int i = 0; i < HID; i += 2) {
                a0 = fmaf(sSpkIC[i],     sWac[i * OUT + tid],       a0);
                a1 = fmaf(sSpkIC[i + 1], sWac[(i + 1) * OUT + tid], a1);
            }
            memAC = beta * memAC + (a0 + a1);
            float spk = (memAC - 1.0f) > 0.0f ? 1.0f : 0.0f;
            memAC -= spk;
            int idx = (b * TSTEPS + t) * OUT + tid;
            out[idx] = spk;
            out[half + idx] = memAC;
        }
        __syncthreads();
    }
}

// ---------------- launch ----------------
extern "C" void kernel_launch(void* const* d_in, const int* in_sizes, int n_in,
                              void* d_out, int out_size) {
    const float* audio = (const float*)d_in[0];
    const float* gt    = (const float*)d_in[1];
    const float* Wb    = (const float*)d_in[2];
    const float* Wic   = (const float*)d_in[3];
    const float* Wac   = (const float*)d_in[4];
    float* out = (float*)d_out;

    int B = in_sizes[0] / NSAMP;   // 256
    int half = out_size / 2;       // B*T*OUT

    sufw_kernel<<<(HID * CCH + 255) / 256, 256>>>(Wb);
    conv_pool_kernel<<<dim3((NCHUNK + GROUP - 1) / GROUP, B), 256>>>(audio, gt);
    snn_kernel<<<B, 64>>>(Wic, Wac, out, half);
}

// round 4
// speedup vs baseline: 2.5335x; 1.0759x over previous
#include <cuda_runtime.h>

// ---------------- problem constants ----------------
#define BATCH   256
#define NSAMP   16000
#define CCH     32
#define KTAP    64
#define NCHUNK  125          // 128-sample chunks covering 16000 samples
#define TSTEPS  124
#define HID     50
#define HIDP    52           // padded row stride for SufW / curB (16B multiple)
#define OUT     10
#define ANS     10

#define GROUP   4            // chunks per conv block
#define SEG     (GROUP*128)  // 512 positions per block
#define SWIN    576          // staged window length per shifted copy
#define SPITCH  592          // padded copy pitch (floats); 592*4 bytes is 16B-aligned

// ---------------- device scratch (no allocs allowed) ----------------
__device__ float S_buf[BATCH * NCHUNK * CCH];                  // per-chunk relu sums
__device__ __align__(16) float SufW_g[CCH * (ANS + 1) * HIDP]; // padded suffix sums

// ---------------- helpers ----------------
__device__ __forceinline__ unsigned s2u(const void* p) {
    return (unsigned)__cvta_generic_to_shared(p);
}
#define FFMA2(acc, a, b) \
    asm("fma.rn.f32x2 %0, %1, %2, %0;" : "+l"(acc) : "l"(a), "l"(b))
#define LDSV2(lo, hi, addr) \
    asm("ld.shared.v2.b64 {%0, %1}, [%2];" : "=l"(lo), "=l"(hi) : "r"(addr))

// ---------------- kernel A: suffix sums of W_bushy (padded layout) ----------------
// SufW_g[(c*11+a)*52 + h] = sum_{a'>=a} W_bushy[h, c*10+a'];  a=10 row = 0; h=50,51 pad = 0
__global__ void sufw_kernel(const float* __restrict__ Wb) {
    int id = blockIdx.x * 256 + threadIdx.x;
    // zero the pad columns and a=10 rows
    for (int r = id; r < CCH * (ANS + 1); r += gridDim.x * 256) {
        SufW_g[r * HIDP + 50] = 0.0f;
        SufW_g[r * HIDP + 51] = 0.0f;
    }
    if (id >= HID * CCH) return;
    int h = id / CCH;
    int c = id % CCH;
    SufW_g[(c * 11 + 10) * HIDP + h] = 0.0f;
    float s = 0.0f;
    #pragma unroll
    for (int a = ANS - 1; a >= 0; a--) {
        s += Wb[h * (CCH * ANS) + c * ANS + a];
        SufW_g[(c * 11 + a) * HIDP + h] = s;
    }
}

// ---------------- kernel B: fused gammatone conv + relu + chunk-sum ----------------
// grid (32, BATCH), 256 threads. lane = channel (audio broadcast across lanes).
// Each warp pass handles 8 positions strided by 4: 23 LDS.128 feed 256 FFMA2.
__global__ void __launch_bounds__(256, 2) conv_pool_kernel(const float* __restrict__ audio,
                                                           const float* __restrict__ gt) {
    const int grp = blockIdx.x;
    const int b   = blockIdx.y;
    __shared__ __align__(16) float s_copy[4][SPITCH];  // 4 shifted copies of audio window
    __shared__ float s_gt[KTAP * 33];                  // swizzled taps [k*33+c]
    __shared__ float s_part[256];

    const int tid = threadIdx.x;
    const int P0  = grp * SEG;
    const float* abase = audio + b * NSAMP;

    #pragma unroll
    for (int s = 0; s < 4; s++) {
        for (int i = tid; i < SWIN; i += 256) {
            int n = P0 - 31 + i + s;
            s_copy[s][i] = (n >= 0 && n < NSAMP) ? abase[n] : 0.0f;
        }
    }
    for (int t = tid; t < CCH * KTAP; t += 256) {
        int c = t >> 6, k = t & 63;
        s_gt[k * 33 + c] = gt[t];
    }
    __syncthreads();

    const int c = tid & 31;   // channel = lane
    const int g = tid >> 5;   // warp id

    unsigned long long kp[32];
    #pragma unroll
    for (int j = 0; j < 32; j++) {
        float t0 = s_gt[(2 * j) * 33 + c];
        float t1 = s_gt[(2 * j + 1) * 33 + c];
        asm("mov.b64 %0, {%1, %2};" : "=l"(kp[j]) : "f"(t0), "f"(t1));
    }

    const unsigned sbase = s2u(&s_copy[0][0]);
    float chunkacc = 0.0f;

    #pragma unroll 1
    for (int pass = 0; pass < 8; pass++) {
        const int h  = pass >> 2;
        const int c4 = pass & 3;
        const int base = g * 64 + 32 * h;
        const unsigned addr = sbase + (unsigned)((c4 * SPITCH + base) * 4);

        unsigned long long accL[8], accH[8];
        #pragma unroll
        for (int j = 0; j < 8; j++) { accL[j] = 0ull; accH[j] = 0ull; }

        #pragma unroll
        for (int u = 0; u < 23; u++) {
            unsigned long long lo, hi;
            LDSV2(lo, hi, addr + 16u * (unsigned)u);
            #pragma unroll
            for (int j = 0; j < 8; j++) {
                const int m = u - j;
                if (m >= 0 && m < 16) {
                    FFMA2(accL[j], lo, kp[2 * m]);
                    FFMA2(accH[j], hi, kp[2 * m + 1]);
                }
            }
        }

        #pragma unroll
        for (int j = 0; j < 8; j++) {
            float l0, l1, h0, h1;
            asm("mov.b64 {%0, %1}, %2;" : "=f"(l0), "=f"(l1) : "l"(accL[j]));
            asm("mov.b64 {%0, %1}, %2;" : "=f"(h0), "=f"(h1) : "l"(accH[j]));
            float y = (l0 + l1) + (h0 + h1);
            chunkacc += fmaxf(y, 0.0f);
        }
    }

    s_part[tid] = chunkacc;
    __syncthreads();

    if (tid < 128) {
        int cg = tid >> 5, cc = tid & 31;
        float s = s_part[cg * 64 + cc] + s_part[cg * 64 + 32 + cc];
        int j = grp * GROUP + cg;
        if (j < NCHUNK)
            S_buf[(b * NCHUNK + j) * CCH + cc] = s;
    }
}

// ---------------- kernel C: LIF scan with hoisted bushy currents ----------------
// one block (64 threads) per batch element.
// phase 0: AN spike-count offsets for all steps (parallel)
// phase 1: curB[t][h] = sum_c SufW[off(t,c) + h]  via LDG.128 gathers (parallel)
// phase 2: 124-step sequential scan, 2 syncthreads per step
__global__ void __launch_bounds__(64) snn_kernel(const float* __restrict__ Wic,
                                                 const float* __restrict__ Wac,
                                                 float* __restrict__ out, int half) {
    const int b = blockIdx.x;
    __shared__ __align__(16) float sCurB[TSTEPS * HIDP];   // 25792 B
    __shared__ float sWic[HID * HID];                      // transposed [i*50 + h]
    __shared__ float sWac[HID * OUT];                      // transposed [i*10 + o]
    __shared__ unsigned short sOff[TSTEPS * CCH];          // 7936 B
    __shared__ float sSpkB[HID];
    __shared__ float sSpkIC[HID];

    const int tid = threadIdx.x;

    // ---- phase 0: per-(t,c) suffix offsets ----
    for (int x = tid; x < TSTEPS * CCH; x += 64) {
        int t = x >> 5, c = x & 31;
        float s0 = S_buf[(b * NCHUNK + t) * CCH + c];
        float s1 = S_buf[(b * NCHUNK + t + 1) * CCH + c];
        float env = (s0 + s1) * (1.0f / 256.0f);
        int cnt = 0;
        #pragma unroll
        for (int a = 0; a < ANS; a++) {
            float sc = 0.5f + (float)a * (1.0f / 9.0f);
            cnt += (env * sc - 0.5f) > 0.0f;
        }
        sOff[x] = (unsigned short)((c * 11 + (ANS - cnt)) * HIDP);
    }
    // weights (independent smem, no barrier needed before)
    for (int x = tid; x < HID * HID; x += 64) {
        int h = x / HID, i = x % HID;
        sWic[i * HID + h] = Wic[x];
    }
    for (int x = tid; x < OUT * HID; x += 64) {
        int o = x / HID, i = x % HID;
        sWac[i * OUT + o] = Wac[x];
    }
    __syncthreads();

    // ---- phase 1: bushy input currents, float4 gathers ----
    for (int x = tid; x < TSTEPS * (HIDP / 4); x += 64) {
        int t = x / (HIDP / 4);
        int q = x - t * (HIDP / 4);
        const unsigned short* off = &sOff[t * CCH];
        float4 acc0 = make_float4(0.f, 0.f, 0.f, 0.f);
        float4 acc1 = make_float4(0.f, 0.f, 0.f, 0.f);
        #pragma unroll 4
        for (int c = 0; c < CCH; c += 2) {
            float4 v0 = __ldg((const float4*)(SufW_g + off[c] + 4 * q));
            float4 v1 = __ldg((const float4*)(SufW_g + off[c + 1] + 4 * q));
            acc0.x += v0.x; acc0.y += v0.y; acc0.z += v0.z; acc0.w += v0.w;
            acc1.x += v1.x; acc1.y += v1.y; acc1.z += v1.z; acc1.w += v1.w;
        }
        float4 r;
        r.x = acc0.x + acc1.x; r.y = acc0.y + acc1.y;
        r.z = acc0.z + acc1.z; r.w = acc0.w + acc1.w;
        *(float4*)&sCurB[t * HIDP + 4 * q] = r;
    }
    __syncthreads();

    // ---- phase 2: sequential LIF scan ----
    float memB = 0.0f, memIC = 0.0f, memAC = 0.0f;
    const float beta = 0.95f;

    for (int t = 0; t < TSTEPS; t++) {
        if (tid < HID) {
            memB = beta * memB + sCurB[t * HIDP + tid];
            float spk = (memB - 1.0f) > 0.0f ? 1.0f : 0.0f;
            memB -= spk;
            sSpkB[tid] = spk;
        }
        __syncthreads();

        if (tid < HID) {
            float a0 = 0.f, a1 = 0.f, a2 = 0.f, a3 = 0.f;
            #pragma unroll
            for (int i = 0; i < 48; i += 4) {
                a0 = fmaf(sSpkB[i],     sWic[i * HID + tid],       a0);
                a1 = fmaf(sSpkB[i + 1], sWic[(i + 1) * HID + tid], a1);
                a2 = fmaf(sSpkB[i + 2], sWic[(i + 2) * HID + tid], a2);
                a3 = fmaf(sSpkB[i + 3], sWic[(i + 3) * HID + tid], a3);
            }
            a0 = fmaf(sSpkB[48], sWic[48 * HID + tid], a0);
            a1 = fmaf(sSpkB[49], sWic[49 * HID + tid], a1);
            memIC = beta * memIC + ((a0 + a1) + (a2 + a3));
            float spk = (memIC - 1.0f) > 0.0f ? 1.0f : 0.0f;
            memIC -= spk;
            sSpkIC[tid] = spk;
        }
        __syncthreads();

        if (tid < OUT) {
            float a0 = 0.f, a1 = 0.f, a2 = 0.f, a3 = 0.f;
            #pragma unroll
            for (int i = 0; i < 48; i += 4) {
                a0 = fmaf(sSpkIC[i],     sWac[i * OUT + tid],       a0);
                a1 = fmaf(sSpkIC[i + 1], sWac[(i + 1) * OUT + tid], a1);
                a2 = fmaf(sSpkIC[i + 2], sWac[(i + 2) * OUT + tid], a2);
                a3 = fmaf(sSpkIC[i + 3], sWac[(i + 3) * OUT + tid], a3);
            }
            a0 = fmaf(sSpkIC[48], sWac[48 * OUT + tid], a0);
            a1 = fmaf(sSpkIC[49], sWac[49 * OUT + tid], a1);
            memAC = beta * memAC + ((a0 + a1) + (a2 + a3));
            float spk = (memAC - 1.0f) > 0.0f ? 1.0f : 0.0f;
            memAC -= spk;
            int idx = (b * TSTEPS + t) * OUT + tid;
            out[idx] = spk;
            out[half + idx] = memAC;
        }
        // no barrier: next bushy only writes sSpkB, whose readers (IC) finished
        // before the last barrier; the next loop's first barrier orders the rest.
    }
}

// ---------------- launch ----------------
extern "C" void kernel_launch(void* const* d_in, const int* in_sizes, int n_in,
                              void* d_out, int out_size) {
    const float* audio = (const float*)d_in[0];
    const float* gt    = (const float*)d_in[1];
    const float* Wb    = (const float*)d_in[2];
    const float* Wic   = (const float*)d_in[3];
    const float* Wac   = (const float*)d_in[4];
    float* out = (float*)d_out;

    int B = in_sizes[0] / NSAMP;   // 256
    int half = out_size / 2;       // B*T*OUT

    sufw_kernel<<<(HID * CCH + 255) / 256, 256>>>(Wb);
    conv_pool_kernel<<<dim3((NCHUNK + GROUP - 1) / GROUP, B), 256>>>(audio, gt);
    snn_kernel<<<B, 64>>>(Wic, Wac, out, half);
}

// round 5
// speedup vs baseline: 2.6958x; 1.0640x over previous
#include <cuda_runtime.h>

// ---------------- problem constants ----------------
#define BATCH   256
#define NSAMP   16000
#define CCH     32
#define KTAP    64
#define NCHUNK  125          // 128-sample chunks covering 16000 samples
#define TSTEPS  124
#define HID     50
#define HIDP    52           // padded row stride for SufW / curB
#define OUT     10
#define ANS     10

#define GROUP   8            // chunks per conv block (one per warp)
#define SEG     (GROUP*128)  // 1024 positions per block
#define SWIN    1088         // staged window length per shifted copy
#define SPITCH  1104         // padded copy pitch (floats); *4 bytes is 16B multiple

// ---------------- device scratch (no allocs allowed) ----------------
__device__ float  S_buf[BATCH * NCHUNK * CCH];                  // per-chunk relu sums
__device__ __align__(16) float S_padtail[CCH];                  // guard (unused)
__device__ __align__(16) float SufW_g[CCH * (ANS + 1) * HIDP];  // padded suffix sums
__device__ __align__(16) float curB_g[BATCH * TSTEPS * HIDP];   // bushy input currents
__device__ __align__(16) float2 W2ic_g[HID * 32];               // packed IC weight columns
__device__ float WacT_g[HID * OUT];                             // transposed AC weights

// ---------------- helpers ----------------
__device__ __forceinline__ unsigned s2u(const void* p) {
    return (unsigned)__cvta_generic_to_shared(p);
}
#define FFMA2(acc, a, b) \
    asm("fma.rn.f32x2 %0, %1, %2, %0;" : "+l"(acc) : "l"(a), "l"(b))
#define LDSV2(lo, hi, addr) \
    asm("ld.shared.v2.b64 {%0, %1}, [%2];" : "=l"(lo), "=l"(hi) : "r"(addr))

// ---------------- kernel A: weight preprocessing ----------------
// - SufW_g[(c*11+a)*52 + h] = sum_{a'>=a} W_bushy[h, c*10+a'] (a=10 row and h=50,51 pads = 0)
// - W2ic_g[i*32+l] = { Wic[l][i], l<18 ? Wic[l+32][i] : 0 }
// - WacT_g[i*10+o] = Wac[o][i]
__global__ void prep_kernel(const float* __restrict__ Wb,
                            const float* __restrict__ Wic,
                            const float* __restrict__ Wac) {
    int id = blockIdx.x * 256 + threadIdx.x;
    if (id < CCH * (ANS + 1)) {               // zero pad columns
        SufW_g[id * HIDP + 50] = 0.0f;
        SufW_g[id * HIDP + 51] = 0.0f;
    }
    if (id < HID * CCH) {                     // suffix sums
        int h = id / CCH;
        int c = id % CCH;
        SufW_g[(c * 11 + 10) * HIDP + h] = 0.0f;
        float s = 0.0f;
        #pragma unroll
        for (int a = ANS - 1; a >= 0; a--) {
            s += Wb[h * (CCH * ANS) + c * ANS + a];
            SufW_g[(c * 11 + a) * HIDP + h] = s;
        }
    }
    if (id >= 1600 && id < 3200) {            // packed IC columns
        int e = id - 1600;
        int i = e >> 5, l = e & 31;
        float x = Wic[l * HID + i];
        float y = (l < 18) ? Wic[(l + 32) * HID + i] : 0.0f;
        W2ic_g[e] = make_float2(x, y);
    }
    if (id >= 3200 && id < 3200 + HID * OUT) {  // transposed AC
        int e = id - 3200;
        int i = e / OUT, o = e % OUT;
        WacT_g[e] = Wac[o * HID + i];
    }
}

// ---------------- kernel B: fused gammatone conv + relu + chunk-sum ----------------
// grid (16, BATCH), 256 threads. lane = channel (audio broadcast across lanes).
// Warp g covers chunk grp*8+g (128 positions). Each pass handles 8 positions
// strided by 4: 23 LDS.128 feed 256 FFMA2. 16 passes per warp, direct store.
__global__ void __launch_bounds__(256, 2) conv_pool_kernel(const float* __restrict__ audio,
                                                           const float* __restrict__ gt) {
    const int grp = blockIdx.x;
    const int b   = blockIdx.y;
    __shared__ __align__(16) float s_copy[4][SPITCH];  // 4 shifted copies of audio window
    __shared__ float s_gt[KTAP * 33];                  // swizzled taps [k*33+c]

    const int tid = threadIdx.x;
    const int P0  = grp * SEG;
    const float* abase = audio + b * NSAMP;

    #pragma unroll
    for (int s = 0; s < 4; s++) {
        for (int i = tid; i < SWIN; i += 256) {
            int n = P0 - 31 + i + s;
            s_copy[s][i] = (n >= 0 && n < NSAMP) ? abase[n] : 0.0f;
        }
    }
    for (int t = tid; t < CCH * KTAP; t += 256) {
        int c = t >> 6, k = t & 63;
        s_gt[k * 33 + c] = gt[t];
    }
    __syncthreads();

    const int c = tid & 31;   // channel = lane
    const int g = tid >> 5;   // warp id = local chunk

    unsigned long long kp[32];
    #pragma unroll
    for (int j = 0; j < 32; j++) {
        float t0 = s_gt[(2 * j) * 33 + c];
        float t1 = s_gt[(2 * j + 1) * 33 + c];
        asm("mov.b64 %0, {%1, %2};" : "=l"(kp[j]) : "f"(t0), "f"(t1));
    }

    const unsigned sbase = s2u(&s_copy[0][0]);
    float chunkacc = 0.0f;

    #pragma unroll 1
    for (int pass = 0; pass < 16; pass++) {
        const int h  = pass >> 2;        // 0..3 : which 32-position quarter
        const int c4 = pass & 3;         // copy index = position mod 4
        const int base = g * 128 + 32 * h;
        const unsigned addr = sbase + (unsigned)((c4 * SPITCH + base) * 4);

        unsigned long long accL[8], accH[8];
        #pragma unroll
        for (int j = 0; j < 8; j++) { accL[j] = 0ull; accH[j] = 0ull; }

        #pragma unroll
        for (int u = 0; u < 23; u++) {
            unsigned long long lo, hi;
            LDSV2(lo, hi, addr + 16u * (unsigned)u);
            #pragma unroll
            for (int j = 0; j < 8; j++) {
                const int m = u - j;
                if (m >= 0 && m < 16) {
                    FFMA2(accL[j], lo, kp[2 * m]);
                    FFMA2(accH[j], hi, kp[2 * m + 1]);
                }
            }
        }

        #pragma unroll
        for (int j = 0; j < 8; j++) {
            float l0, l1, h0, h1;
            asm("mov.b64 {%0, %1}, %2;" : "=f"(l0), "=f"(l1) : "l"(accL[j]));
            asm("mov.b64 {%0, %1}, %2;" : "=f"(h0), "=f"(h1) : "l"(accH[j]));
            float y = (l0 + l1) + (h0 + h1);
            chunkacc += fmaxf(y, 0.0f);
        }
    }

    const int j = grp * GROUP + g;
    if (j < NCHUNK)
        S_buf[(b * NCHUNK + j) * CCH + c] = chunkacc;
}

// ---------------- kernel C: bushy input currents (parallel gather) ----------------
// grid (BATCH), 256 threads. curB_g[b][t][h] = sum_c SufW[off(b,t,c) + h]
__global__ void __launch_bounds__(256) curb_kernel() {
    const int b = blockIdx.x;
    __shared__ unsigned short sOff[TSTEPS * CCH];
    const int tid = threadIdx.x;

    for (int x = tid; x < TSTEPS * CCH; x += 256) {
        int t = x >> 5, c = x & 31;
        float s0 = S_buf[(b * NCHUNK + t) * CCH + c];
        float s1 = S_buf[(b * NCHUNK + t + 1) * CCH + c];
        float env = (s0 + s1) * (1.0f / 256.0f);
        int cnt = 0;
        #pragma unroll
        for (int a = 0; a < ANS; a++) {
            float sc = 0.5f + (float)a * (1.0f / 9.0f);
            cnt += (env * sc - 0.5f) > 0.0f;
        }
        sOff[x] = (unsigned short)((c * 11 + (ANS - cnt)) * HIDP);
    }
    __syncthreads();

    for (int x = tid; x < TSTEPS * (HIDP / 4); x += 256) {
        int t = x / (HIDP / 4);
        int q = x - t * (HIDP / 4);
        const unsigned short* off = &sOff[t * CCH];
        float4 acc0 = make_float4(0.f, 0.f, 0.f, 0.f);
        float4 acc1 = make_float4(0.f, 0.f, 0.f, 0.f);
        #pragma unroll 4
        for (int c = 0; c < CCH; c += 2) {
            float4 v0 = __ldg((const float4*)(SufW_g + off[c] + 4 * q));
            float4 v1 = __ldg((const float4*)(SufW_g + off[c + 1] + 4 * q));
            acc0.x += v0.x; acc0.y += v0.y; acc0.z += v0.z; acc0.w += v0.w;
            acc1.x += v1.x; acc1.y += v1.y; acc1.z += v1.z; acc1.w += v1.w;
        }
        float4 r;
        r.x = acc0.x + acc1.x; r.y = acc0.y + acc1.y;
        r.z = acc0.z + acc1.z; r.w = acc0.w + acc1.w;
        *(float4*)&curB_g[b * (TSTEPS * HIDP) + t * HIDP + 4 * q] = r;
    }
}

// ---------------- kernel D: warp-per-batch LIF scan (no block barriers) ----------------
// grid (BATCH), 32 threads. lane l owns hidden units l and l+32.
__global__ void __launch_bounds__(32) scan_kernel(float* __restrict__ out, int half) {
    const int b = blockIdx.x;
    __shared__ __align__(16) float  sCurB[TSTEPS * HIDP + 16];  // +16 pad (last-row overread)
    __shared__ __align__(16) float2 sW2[HID * 32];
    __shared__ float sWacT[HID * OUT];
    __shared__ __align__(8) float sSpkB[52];
    __shared__ __align__(8) float sSpkIC[52];

    const int l = threadIdx.x;

    // stage currents + weights (coalesced float4)
    {
        const float4* src = (const float4*)(curB_g + b * (TSTEPS * HIDP));
        float4* dst = (float4*)sCurB;
        for (int i = l; i < (TSTEPS * HIDP) / 4; i += 32) dst[i] = __ldg(src + i);
        if (l < 16) sCurB[TSTEPS * HIDP + l] = 0.0f;
        const float4* wsrc = (const float4*)W2ic_g;   // 800 float4
        float4* wdst = (float4*)sW2;
        for (int i = l; i < (HID * 32 * 2) / 4; i += 32) wdst[i] = __ldg(wsrc + i);
        for (int i = l; i < HID * OUT; i += 32) sWacT[i] = WacT_g[i];
    }
    __syncwarp();

    float memB0 = 0.f, memB1 = 0.f, memIC0 = 0.f, memIC1 = 0.f, memAC = 0.f;
    const bool lane18 = (l < 18);
    const bool lane10 = (l < 10);
    const float beta = 0.95f;

    for (int t = 0; t < TSTEPS; t++) {
        const float* cb = sCurB + t * HIDP;
        // ---- bushy LIF ----
        float cur0 = cb[l];
        float cur1 = cb[32 + l];          // lanes >=18 read junk; never used
        memB0 = fmaf(beta, memB0, cur0);
        memB1 = fmaf(beta, memB1, cur1);
        float s0 = (memB0 > 1.0f) ? 1.0f : 0.0f;
        float s1 = (memB1 > 1.0f) ? 1.0f : 0.0f;
        memB0 -= s0; memB1 -= s1;
        sSpkB[l] = s0;
        if (lane18) sSpkB[32 + l] = s1;
        __syncwarp();

        // ---- inferior colliculus LIF ----
        float ica = 0.f, icb = 0.f, icc = 0.f, icd = 0.f;
        #pragma unroll
        for (int i = 0; i < HID; i += 2) {
            float2 sp = *(const float2*)&sSpkB[i];
            float2 wA = sW2[i * 32 + l];
            float2 wB = sW2[(i + 1) * 32 + l];
            ica = fmaf(sp.x, wA.x, ica);
            icb = fmaf(sp.x, wA.y, icb);
            icc = fmaf(sp.y, wB.x, icc);
            icd = fmaf(sp.y, wB.y, icd);
        }
        memIC0 = fmaf(beta, memIC0, ica + icc);
        memIC1 = fmaf(beta, memIC1, icb + icd);
        float u0 = (memIC0 > 1.0f) ? 1.0f : 0.0f;
        float u1 = (memIC1 > 1.0f) ? 1.0f : 0.0f;
        memIC0 -= u0; memIC1 -= u1;
        sSpkIC[l] = u0;
        if (lane18) sSpkIC[32 + l] = u1;   // lanes>=18: weights padded 0 -> u1 = 0 anyway
        __syncwarp();

        // ---- audio cortex LIF + output ----
        if (lane10) {
            float aa = 0.f, ab = 0.f;
            #pragma unroll
            for (int i = 0; i < HID; i += 2) {
                float2 sp = *(const float2*)&sSpkIC[i];
                aa = fmaf(sp.x, sWacT[i * OUT + l], aa);
                ab = fmaf(sp.y, sWacT[(i + 1) * OUT + l], ab);
            }
            memAC = fmaf(beta, memAC, aa + ab);
            float sa = (memAC > 1.0f) ? 1.0f : 0.0f;
            memAC -= sa;
            int idx = (b * TSTEPS + t) * OUT + l;
            out[idx] = sa;
            out[half + idx] = memAC;
        }
        // no trailing sync needed: next sSpkB write is ordered by this step's
        // syncwarp #2; sSpkIC's next write is ordered by next step's syncwarp #1.
    }
}

// ---------------- launch ----------------
extern "C" void kernel_launch(void* const* d_in, const int* in_sizes, int n_in,
                              void* d_out, int out_size) {
    const float* audio = (const float*)d_in[0];
    const float* gt    = (const float*)d_in[1];
    const float* Wb    = (const float*)d_in[2];
    const float* Wic   = (const float*)d_in[3];
    const float* Wac   = (const float*)d_in[4];
    float* out = (float*)d_out;

    int B = in_sizes[0] / NSAMP;   // 256
    int half = out_size / 2;       // B*T*OUT

    prep_kernel<<<15, 256>>>(Wb, Wic, Wac);
    conv_pool_kernel<<<dim3((NCHUNK + GROUP - 1) / GROUP, B), 256>>>(audio, gt);
    curb_kernel<<<B, 256>>>();
    scan_kernel<<<B, 32>>>(out, half);
}

// round 6
// speedup vs baseline: 2.9012x; 1.0762x over previous
#include <cuda_runtime.h>

// ---------------- problem constants ----------------
#define BATCH   256
#define NSAMP   16000
#define CCH     32
#define KTAP    64
#define NCHUNK  125          // 128-sample chunks covering 16000 samples
#define TSTEPS  124
#define HID     50
#define HIDP    52           // padded row stride for SufW / curB
#define OUT     10
#define ANS     10

#define GROUP   8            // chunks per conv block (one per warp)
#define SEG     (GROUP*128)  // 1024 positions per block
#define SWIN    1088         // staged window length per shifted copy
#define SPITCH  1104         // padded copy pitch (floats); *4 bytes is 16B multiple

// ---------------- device scratch (no allocs allowed) ----------------
__device__ float  S_buf[BATCH * NCHUNK * CCH];                  // per-chunk relu sums
__device__ __align__(16) float SufW_g[CCH * (ANS + 1) * HIDP];  // padded suffix sums

// ---------------- helpers ----------------
__device__ __forceinline__ unsigned s2u(const void* p) {
    return (unsigned)__cvta_generic_to_shared(p);
}
#define FFMA2(acc, a, b) \
    asm("fma.rn.f32x2 %0, %1, %2, %0;" : "+l"(acc) : "l"(a), "l"(b))
#define LDSV2(lo, hi, addr) \
    asm("ld.shared.v2.b64 {%0, %1}, [%2];" : "=l"(lo), "=l"(hi) : "r"(addr))

// ---------------- kernel A: suffix sums of W_bushy (padded layout) ----------------
__global__ void prep_kernel(const float* __restrict__ Wb) {
    int id = blockIdx.x * 256 + threadIdx.x;
    if (id < CCH * (ANS + 1)) {               // zero pad columns
        SufW_g[id * HIDP + 50] = 0.0f;
        SufW_g[id * HIDP + 51] = 0.0f;
    }
    if (id >= HID * CCH) return;
    int h = id / CCH;
    int c = id % CCH;
    SufW_g[(c * 11 + 10) * HIDP + h] = 0.0f;
    float s = 0.0f;
    #pragma unroll
    for (int a = ANS - 1; a >= 0; a--) {
        s += Wb[h * (CCH * ANS) + c * ANS + a];
        SufW_g[(c * 11 + a) * HIDP + h] = s;
    }
}

// ---------------- kernel B: fused gammatone conv + relu + chunk-sum ----------------
__global__ void __launch_bounds__(256, 2) conv_pool_kernel(const float* __restrict__ audio,
                                                           const float* __restrict__ gt) {
    const int grp = blockIdx.x;
    const int b   = blockIdx.y;
    __shared__ __align__(16) float s_copy[4][SPITCH];  // 4 shifted copies of audio window
    __shared__ float s_gt[KTAP * 33];                  // swizzled taps [k*33+c]

    const int tid = threadIdx.x;
    const int P0  = grp * SEG;
    const float* abase = audio + b * NSAMP;

    #pragma unroll
    for (int s = 0; s < 4; s++) {
        for (int i = tid; i < SWIN; i += 256) {
            int n = P0 - 31 + i + s;
            s_copy[s][i] = (n >= 0 && n < NSAMP) ? abase[n] : 0.0f;
        }
    }
    for (int t = tid; t < CCH * KTAP; t += 256) {
        int c = t >> 6, k = t & 63;
        s_gt[k * 33 + c] = gt[t];
    }
    __syncthreads();

    const int c = tid & 31;   // channel = lane
    const int g = tid >> 5;   // warp id = local chunk

    unsigned long long kp[32];
    #pragma unroll
    for (int j = 0; j < 32; j++) {
        float t0 = s_gt[(2 * j) * 33 + c];
        float t1 = s_gt[(2 * j + 1) * 33 + c];
        asm("mov.b64 %0, {%1, %2};" : "=l"(kp[j]) : "f"(t0), "f"(t1));
    }

    const unsigned sbase = s2u(&s_copy[0][0]);
    float chunkacc = 0.0f;

    #pragma unroll 1
    for (int pass = 0; pass < 16; pass++) {
        const int h  = pass >> 2;
        const int c4 = pass & 3;
        const int base = g * 128 + 32 * h;
        const unsigned addr = sbase + (unsigned)((c4 * SPITCH + base) * 4);

        unsigned long long accL[8], accH[8];
        #pragma unroll
        for (int j = 0; j < 8; j++) { accL[j] = 0ull; accH[j] = 0ull; }

        #pragma unroll
        for (int u = 0; u < 23; u++) {
            unsigned long long lo, hi;
            LDSV2(lo, hi, addr + 16u * (unsigned)u);
            #pragma unroll
            for (int j = 0; j < 8; j++) {
                const int m = u - j;
                if (m >= 0 && m < 16) {
                    FFMA2(accL[j], lo, kp[2 * m]);
                    FFMA2(accH[j], hi, kp[2 * m + 1]);
                }
            }
        }

        #pragma unroll
        for (int j = 0; j < 8; j++) {
            float l0, l1, h0, h1;
            asm("mov.b64 {%0, %1}, %2;" : "=f"(l0), "=f"(l1) : "l"(accL[j]));
            asm("mov.b64 {%0, %1}, %2;" : "=f"(h0), "=f"(h1) : "l"(accH[j]));
            float y = (l0 + l1) + (h0 + h1);
            chunkacc += fmaxf(y, 0.0f);
        }
    }

    const int j = grp * GROUP + g;
    if (j < NCHUNK)
        S_buf[(b * NCHUNK + j) * CCH + c] = chunkacc;
}

// ---------------- kernel C: merged gather + warp scan, one block per batch ----------------
// 128 threads: phase 0 AN offsets, phase 1 SufW gather -> sCurB (smem),
// then warps 1-3 exit and warp 0 runs the 124-step LIF scan with all
// IC/AC weights held in registers.
__global__ void __launch_bounds__(128, 2) scan_kernel(const float* __restrict__ Wic,
                                                      const float* __restrict__ Wac,
                                                      float* __restrict__ out, int half) {
    const int b = blockIdx.x;
    __shared__ __align__(16) float  sCurB[TSTEPS * HIDP];
    __shared__ unsigned short sOff[TSTEPS * CCH];
    __shared__ __align__(8) float sSpkB[52];
    __shared__ __align__(8) float sSpkIC[52];

    const int tid = threadIdx.x;

    // ---- phase 0: per-(t,c) suffix offsets ----
    for (int x = tid; x < TSTEPS * CCH; x += 128) {
        int t = x >> 5, c = x & 31;
        float s0 = S_buf[(b * NCHUNK + t) * CCH + c];
        float s1 = S_buf[(b * NCHUNK + t + 1) * CCH + c];
        float env = (s0 + s1) * (1.0f / 256.0f);
        int cnt = 0;
        #pragma unroll
        for (int a = 0; a < ANS; a++) {
            float sc = 0.5f + (float)a * (1.0f / 9.0f);
            cnt += (env * sc - 0.5f) > 0.0f;
        }
        sOff[x] = (unsigned short)((c * 11 + (ANS - cnt)) * HIDP);
    }
    __syncthreads();

    // ---- phase 1: bushy input currents into smem ----
    for (int x = tid; x < TSTEPS * (HIDP / 4); x += 128) {
        int t = x / (HIDP / 4);
        int q = x - t * (HIDP / 4);
        const unsigned short* off = &sOff[t * CCH];
        float4 acc0 = make_float4(0.f, 0.f, 0.f, 0.f);
        float4 acc1 = make_float4(0.f, 0.f, 0.f, 0.f);
        #pragma unroll 4
        for (int c = 0; c < CCH; c += 2) {
            float4 v0 = __ldg((const float4*)(SufW_g + off[c] + 4 * q));
            float4 v1 = __ldg((const float4*)(SufW_g + off[c + 1] + 4 * q));
            acc0.x += v0.x; acc0.y += v0.y; acc0.z += v0.z; acc0.w += v0.w;
            acc1.x += v1.x; acc1.y += v1.y; acc1.z += v1.z; acc1.w += v1.w;
        }
        float4 r;
        r.x = acc0.x + acc1.x; r.y = acc0.y + acc1.y;
        r.z = acc0.z + acc1.z; r.w = acc0.w + acc1.w;
        *(float4*)&sCurB[t * HIDP + 4 * q] = r;
    }
    __syncthreads();

    if (tid >= 32) return;      // warps 1-3 done
    const int l = tid;

    // ---- load weights into registers (unrolled, compile-time indices) ----
    const bool lane18 = (l < 18);
    const bool lane10 = (l < 10);
    // IC: unit l row and unit l+32 row (zeros for lanes >= 18)
    float2 wA[25], wB[25], wC[25];
    {
        const float* rowA = Wic + l * HID;
        const float* rowB = Wic + (lane18 ? (l + 32) : l) * HID;
        const float* rowC = Wac + (lane10 ? l : 0) * HID;
        #pragma unroll
        for (int j = 0; j < 25; j++) {
            wA[j] = make_float2(__ldg(rowA + 2 * j), __ldg(rowA + 2 * j + 1));
            float2 vb = make_float2(__ldg(rowB + 2 * j), __ldg(rowB + 2 * j + 1));
            wB[j] = lane18 ? vb : make_float2(0.f, 0.f);
            wC[j] = make_float2(__ldg(rowC + 2 * j), __ldg(rowC + 2 * j + 1));
        }
    }

    float memB0 = 0.f, memB1 = 0.f, memIC0 = 0.f, memIC1 = 0.f, memAC = 0.f;
    const float beta = 0.95f;

    for (int t = 0; t < TSTEPS; t++) {
        const float* cb = sCurB + t * HIDP;
        // ---- bushy LIF ----
        float cur0 = cb[l];
        float cur1 = cb[32 + l];          // lanes >=18 read pad/junk; never used
        memB0 = fmaf(beta, memB0, cur0);
        memB1 = fmaf(beta, memB1, cur1);
        float s0 = (memB0 > 1.0f) ? 1.0f : 0.0f;
        float s1 = (memB1 > 1.0f) ? 1.0f : 0.0f;
        memB0 -= s0; memB1 -= s1;
        sSpkB[l] = s0;
        if (lane18) sSpkB[32 + l] = s1;
        __syncwarp();

        // ---- inferior colliculus LIF (register weights) ----
        {
            float a0 = 0.f, a1 = 0.f, a2 = 0.f, a3 = 0.f;
            #pragma unroll
            for (int j = 0; j < 25; j++) {
                float2 sp = *(const float2*)&sSpkB[2 * j];
                a0 = fmaf(sp.x, wA[j].x, a0);
                a1 = fmaf(sp.y, wA[j].y, a1);
                a2 = fmaf(sp.x, wB[j].x, a2);
                a3 = fmaf(sp.y, wB[j].y, a3);
            }
            memIC0 = fmaf(beta, memIC0, a0 + a1);
            memIC1 = fmaf(beta, memIC1, a2 + a3);
        }
        float u0 = (memIC0 > 1.0f) ? 1.0f : 0.0f;
        float u1 = (memIC1 > 1.0f) ? 1.0f : 0.0f;
        memIC0 -= u0; memIC1 -= u1;
        sSpkIC[l] = u0;
        if (lane18) sSpkIC[32 + l] = u1;
        __syncwarp();

        // ---- audio cortex LIF + output ----
        {
            float a0 = 0.f, a1 = 0.f;
            #pragma unroll
            for (int j = 0; j < 25; j++) {
                float2 sp = *(const float2*)&sSpkIC[2 * j];
                a0 = fmaf(sp.x, wC[j].x, a0);
                a1 = fmaf(sp.y, wC[j].y, a1);
            }
            memAC = fmaf(beta, memAC, a0 + a1);
            float sa = (memAC > 1.0f) ? 1.0f : 0.0f;
            memAC -= sa;
            if (lane10) {
                int idx = (b * TSTEPS + t) * OUT + l;
                out[idx] = sa;
                out[half + idx] = memAC;
            }
        }
        // no trailing sync needed: next writes are ordered by the two
        // syncwarps of this/next iteration relative to their readers.
    }
}

// ---------------- launch ----------------
extern "C" void kernel_launch(void* const* d_in, const int* in_sizes, int n_in,
                              void* d_out, int out_size) {
    const float* audio = (const float*)d_in[0];
    const float* gt    = (const float*)d_in[1];
    const float* Wb    = (const float*)d_in[2];
    const float* Wic   = (const float*)d_in[3];
    const float* Wac   = (const float*)d_in[4];
    float* out = (float*)d_out;

    int B = in_sizes[0] / NSAMP;   // 256
    int half = out_size / 2;       // B*T*OUT

    prep_kernel<<<7, 256>>>(Wb);
    conv_pool_kernel<<<dim3((NCHUNK + GROUP - 1) / GROUP, B), 256>>>(audio, gt);
    scan_kernel<<<B, 128>>>(Wic, Wac, out, half);
}